// round 15
// baseline (speedup 1.0000x reference)
#include <cuda_runtime.h>
#include <cstdint>

#define MN       1024
#define BATCH    2048
#define DIM      128
#define NITER_F  100.0f
#define ALPHA_F  0.3f
#define SIGMA_F  16.0f

// ---------------- scratch ----------------
__device__ unsigned long long g_part[16][BATCH]; // per-cell-block argmin partials
__device__ float g_S[MN * DIM];
__device__ float g_cnt[MN];

__device__ __forceinline__ unsigned int f2ord(float f) {
    unsigned int u = __float_as_uint(f);
    return (u & 0x80000000u) ? ~u : (u | 0x80000000u);
}

__device__ __forceinline__ float tf32_rna(float v) {
    uint32_t u;
    asm("cvt.rna.tf32.f32 %0, %1;" : "=r"(u) : "f"(v));
    return __uint_as_float(u);
}

__device__ __forceinline__ void mma_tf32(float* d, const uint32_t* a,
                                         uint32_t b0, uint32_t b1) {
    asm volatile(
        "mma.sync.aligned.m16n8k8.row.col.f32.tf32.tf32.f32 "
        "{%0,%1,%2,%3}, {%4,%5,%6,%7}, {%8,%9}, {%0,%1,%2,%3};"
        : "+f"(d[0]), "+f"(d[1]), "+f"(d[2]), "+f"(d[3])
        : "r"(a[0]), "r"(a[1]), "r"(a[2]), "r"(a[3]), "r"(b0), "r"(b1));
}

// smem tile geometry (hi only): rows x 64 k pair-interleaved, stride 72 floats
#define TSTR 72
#define XTILE_F (128 * TSTR)     // 9216 f
#define WTILE_F (64 * TSTR)      // 4608 f
#define OFF_XHI 0
#define OFF_WHI (OFF_XHI + XTILE_F)
#define OFF_W2S (OFF_WHI + WTILE_F)      // [64]
#define OFF_WMX (OFF_W2S + 64)           // [1]
#define BMU_SMEM_F (OFF_WMX + 4)

// ---------------- K1: BMU approx GEMM (1-pass tf32) + exact refinement -----
// block: 128 batch rows x 64 cells, 8 warps, each 16 rows x 64 cells.
// smem ~55.6KB -> 3-4 CTAs/SM. Approx d2 from hi*hi tf32 MMA; any cell
// within a provable error margin of the row's approx min is re-evaluated
// exactly (fp32 dot from global), so the emitted partial is the EXACT min.
__global__ __launch_bounds__(256, 3)
void k_bmu(const float* __restrict__ x, const float* __restrict__ w) {
    extern __shared__ float smem[];
    float* w2s = smem + OFF_W2S;

    const int tid  = threadIdx.x;
    const int wrp  = tid >> 5;           // 0..7
    const int lane = tid & 31;
    const int gid  = lane >> 2;          // 0..7
    const int tig  = lane & 3;           // 0..3
    const int b0 = blockIdx.x * 128;     // batch tile
    const int m0 = blockIdx.y * 64;      // cell tile
    const uint32_t qmask_q = 0xFu << (lane & ~3);  // quad member mask

    // fold scratch zeroing into this kernel: 256 blocks x 512 floats = all g_S
    {
        int z = blockIdx.y * 16 + blockIdx.x;            // 0..255
        if (tid < 128)
            *(float4*)&g_S[z * 512 + tid * 4] = make_float4(0.f, 0.f, 0.f, 0.f);
        if (tid == 255)
            *(float4*)&g_cnt[z * 4] = make_float4(0.f, 0.f, 0.f, 0.f);
    }

    // exact w2 for this block's 64 cells (fp32, from global)
    if (tid < 64) {
        float s = 0.0f;
        #pragma unroll
        for (int g = 0; g < 32; g++) {
            float4 v = *(const float4*)&w[(m0 + tid) * DIM + g * 4];
            s += v.x * v.x + v.y * v.y + v.z * v.z + v.w * v.w;
        }
        w2s[tid] = s;
    }

    float acc[8][4];
    #pragma unroll
    for (int t = 0; t < 8; t++)
        #pragma unroll
        for (int j = 0; j < 4; j++) acc[t][j] = 0.0f;

    #pragma unroll 1
    for (int c = 0; c < 2; c++) {
        const int kc = c * 64;
        if (c) __syncthreads();   // protect tiles while prior mma reads

        // stage X chunk (hi only): 128 rows x 16 q -> 8 per thread
        #pragma unroll
        for (int i = 0; i < 8; i++) {
            int idx = tid + i * 256;
            int row = idx >> 4;
            int q   = idx & 15;
            int base = row * TSTR + (q >> 1) * 8 + (q & 1);
            float4 xv = *(const float4*)&x[(b0 + row) * DIM + kc + q * 4];
            smem[OFF_XHI + base + 0] = tf32_rna(xv.x);
            smem[OFF_XHI + base + 2] = tf32_rna(xv.y);
            smem[OFF_XHI + base + 4] = tf32_rna(xv.z);
            smem[OFF_XHI + base + 6] = tf32_rna(xv.w);
        }
        // stage W chunk (hi only): 64 rows x 16 q -> 4 per thread
        #pragma unroll
        for (int i = 0; i < 4; i++) {
            int idx = tid + i * 256;
            int row = idx >> 4;
            int q   = idx & 15;
            int base = row * TSTR + (q >> 1) * 8 + (q & 1);
            float4 wv = *(const float4*)&w[(m0 + row) * DIM + kc + q * 4];
            smem[OFF_WHI + base + 0] = tf32_rna(wv.x);
            smem[OFF_WHI + base + 2] = tf32_rna(wv.y);
            smem[OFF_WHI + base + 4] = tf32_rna(wv.z);
            smem[OFF_WHI + base + 6] = tf32_rna(wv.w);
        }
        if (c == 0 && tid == 0) {   // w2max for the margin (after w2s? no:
            // w2s is written pre-loop by this thread group; ensure via sync)
        }
        __syncthreads();
        if (c == 0 && tid == 0) {
            float mx = 0.0f;
            #pragma unroll
            for (int i = 0; i < 64; i++) mx = fmaxf(mx, w2s[i]);
            smem[OFF_WMX] = mx;
        }

        // mainloop: single hi*hi pass
        #pragma unroll
        for (int g = 0; g < 8; g++) {
            const int apos = (wrp * 16 + gid) * TSTR + g * 8 + tig * 2;
            float2 h0 = *(const float2*)&smem[OFF_XHI + apos];
            float2 h1 = *(const float2*)&smem[OFF_XHI + apos + 8 * TSTR];
            uint32_t ah[4];
            ah[0] = __float_as_uint(h0.x); ah[1] = __float_as_uint(h1.x);
            ah[2] = __float_as_uint(h0.y); ah[3] = __float_as_uint(h1.y);
            #pragma unroll
            for (int t = 0; t < 8; t++) {
                const int bpos = (t * 8 + gid) * TSTR + g * 8 + tig * 2;
                float2 bh = *(const float2*)&smem[OFF_WHI + bpos];
                mma_tf32(acc[t], ah, __float_as_uint(bh.x),
                                      __float_as_uint(bh.y));
            }
        }
    }
    __syncthreads();   // w2max visible; tiles no longer needed

    const float w2max = smem[OFF_WMX];

    // epilogue per row: approx min -> margin -> exact refinement of candidates
    #pragma unroll 1
    for (int rp = 0; rp < 2; rp++) {
        const int row = wrp * 16 + rp * 8 + gid;

        // cache this row's x slice: k = tig*32 .. tig*32+31
        float4 xr[8];
        const float4* xp = (const float4*)&x[(b0 + row) * DIM + tig * 32];
        #pragma unroll
        for (int j = 0; j < 8; j++) xr[j] = xp[j];
        float x2p = 0.0f;
        #pragma unroll
        for (int j = 0; j < 8; j++)
            x2p += xr[j].x * xr[j].x + xr[j].y * xr[j].y
                 + xr[j].z * xr[j].z + xr[j].w * xr[j].w;
        x2p += __shfl_xor_sync(0xffffffffu, x2p, 1);
        x2p += __shfl_xor_sync(0xffffffffu, x2p, 2);

        // 2M margin: |approx-exact| <= 2^-9 * ||x|| * ||w||, safety 1.5x
        const float M2 = 2.0f * 1.5f * 0.001953125f * sqrtf(x2p * w2max);

        // approx d2 for this thread's 16 cells; row approx-min
        float dv[16];
        float amin = 3.4e38f;
        #pragma unroll
        for (int t = 0; t < 8; t++) {
            int c0 = t * 8 + tig * 2;
            dv[t * 2 + 0] = w2s[c0]     - 2.0f * acc[t][rp * 2 + 0];
            dv[t * 2 + 1] = w2s[c0 + 1] - 2.0f * acc[t][rp * 2 + 1];
            amin = fminf(amin, fminf(dv[t * 2], dv[t * 2 + 1]));
        }
        amin = fminf(amin, __shfl_xor_sync(0xffffffffu, amin, 1));
        amin = fminf(amin, __shfl_xor_sync(0xffffffffu, amin, 2));

        // qualifying-cell bitmask (bit b: t = b>>1, half = b&1)
        uint32_t qm = 0;
        #pragma unroll
        for (int b = 0; b < 16; b++)
            if (dv[b] <= amin + M2) qm |= (1u << b);

        // quad-cooperative exact refinement of every candidate
        unsigned long long rowbest = 0xFFFFFFFFFFFFFFFFULL;
        #pragma unroll 1
        for (int src = 0; src < 4; src++) {
            uint32_t m = __shfl_sync(qmask_q, qm, (lane & ~3) | src);
            while (m) {
                int b = __ffs(m) - 1;
                m &= m - 1;
                int cl = (b >> 1) * 8 + src * 2 + (b & 1);   // cell in block
                const float4* wp =
                    (const float4*)&w[(m0 + cl) * DIM + tig * 32];
                float p = 0.0f;
                #pragma unroll
                for (int j = 0; j < 8; j++) {
                    float4 wv = wp[j];
                    p += xr[j].x * wv.x + xr[j].y * wv.y
                       + xr[j].z * wv.z + xr[j].w * wv.w;
                }
                p += __shfl_xor_sync(qmask_q, p, 1);
                p += __shfl_xor_sync(qmask_q, p, 2);
                float d2e = w2s[cl] - 2.0f * p;
                unsigned long long key =
                    ((unsigned long long)f2ord(d2e) << 32) |
                    (unsigned long long)(m0 + cl);
                rowbest = min(rowbest, key);
            }
        }
        if (tig == 0)
            g_part[blockIdx.y][b0 + row] = rowbest;
    }
}

// ---------------- K2: reduce partials + scatter x rows into BMU bins --------
__global__ void k_scatter(const float* __restrict__ x) {
    int warp = (blockIdx.x * blockDim.x + threadIdx.x) >> 5;  // 0..2047
    int lane = threadIdx.x & 31;
    if (warp >= BATCH) return;

    unsigned long long v = (lane < 16) ? g_part[lane][warp]
                                       : 0xFFFFFFFFFFFFFFFFULL;
    #pragma unroll
    for (int o = 8; o >= 1; o >>= 1)
        v = min(v, __shfl_xor_sync(0xffffffffu, v, o));
    v = __shfl_sync(0xffffffffu, v, 0);
    int m = (int)(v & 0xFFFFFFFFULL);

    float4 vv = *(const float4*)&x[warp * DIM + lane * 4];
    float* dst = &g_S[m * DIM + lane * 4];
    asm volatile("red.global.add.v4.f32 [%0], {%1, %2, %3, %4};"
                 :: "l"(dst), "f"(vv.x), "f"(vv.y), "f"(vv.z), "f"(vv.w)
                 : "memory");
    if (lane == 0) atomicAdd(&g_cnt[m], 1.0f);
}

// ---------------- K3: fused separable gaussian contraction + update ---------
// 128 blocks = (cx, d-quarter), 256 threads.
__global__ __launch_bounds__(256)
void k_tail(const float* __restrict__ w,
            const int* __restrict__ it,
            float* __restrict__ out) {
    __shared__ float4 Ts[32][9];     // [by][dq], padded
    __shared__ float tc_s[32];
    __shared__ float e_s[32];

    const int cx = blockIdx.x & 31;
    const int d0 = (blockIdx.x >> 5) * 32;   // d-quarter base
    const int tid = threadIdx.x;

    float lr_decay = 1.0f - (float)it[0] / NITER_F;
    float alpha_op = ALPHA_F * lr_decay;
    float sig = SIGMA_F * lr_decay;
    float inv_s2 = 1.0f / (sig * sig);

    if (tid < 32) e_s[tid] = expf(-(float)(tid * tid) * inv_s2);
    __syncthreads();

    // stage A: Ts[by][d] = sum_bx e(|cx-bx|) * S[by*32+bx][d]
    {
        const int by = tid >> 3;           // 0..31
        const int dq = tid & 7;            // float4 index
        const int d  = d0 + dq * 4;
        float4 a = make_float4(0.f, 0.f, 0.f, 0.f);
        #pragma unroll
        for (int bb = 0; bb < 4; bb++) {
            float4 sv[8];
            #pragma unroll
            for (int j = 0; j < 8; j++)
                sv[j] = *(const float4*)&g_S[(by * 32 + bb * 8 + j) * DIM + d];
            #pragma unroll
            for (int j = 0; j < 8; j++) {
                float e = e_s[abs(cx - (bb * 8 + j))];
                a.x += e * sv[j].x; a.y += e * sv[j].y;
                a.z += e * sv[j].z; a.w += e * sv[j].w;
            }
        }
        Ts[by][dq] = a;
    }
    if (tid < 32) {
        float c = 0.0f;
        #pragma unroll
        for (int bx = 0; bx < 32; bx++)
            c += e_s[abs(cx - bx)] * g_cnt[tid * 32 + bx];
        tc_s[tid] = c;
    }
    __syncthreads();

    // stage B
    {
        const int cy = tid >> 3;
        const int dq = tid & 7;
        const int d  = d0 + dq * 4;
        float4 a = make_float4(0.f, 0.f, 0.f, 0.f);
        float s = 0.0f;
        #pragma unroll
        for (int by = 0; by < 32; by++) {
            float e = e_s[abs(cy - by)];
            float4 t = Ts[by][dq];
            a.x += e * t.x; a.y += e * t.y;
            a.z += e * t.z; a.w += e * t.w;
            s += e * tc_s[by];
        }
        const int c = (cy * 32 + cx) * DIM + d;
        float4 wv = *(const float4*)&w[c];
        float4 o;
        o.x = wv.x + alpha_op * (a.x - s * wv.x);
        o.y = wv.y + alpha_op * (a.y - s * wv.y);
        o.z = wv.z + alpha_op * (a.z - s * wv.z);
        o.w = wv.w + alpha_op * (a.w - s * wv.w);
        *(float4*)&out[c] = o;
    }
}

// ---------------- launch ----------------
extern "C" void kernel_launch(void* const* d_in, const int* in_sizes, int n_in,
                              void* d_out, int out_size) {
    const float* x   = (const float*)d_in[0];   // [2048,128]
    const float* w   = (const float*)d_in[1];   // [1024,128]
    const int*   it  = (const int*)d_in[3];
    float* out = (float*)d_out;

    const int bmu_smem = BMU_SMEM_F * 4;   // ~55.6KB
    cudaFuncSetAttribute(k_bmu, cudaFuncAttributeMaxDynamicSharedMemorySize,
                         bmu_smem);

    k_bmu<<<dim3(16, 16), 256, bmu_smem>>>(x, w);
    k_scatter<<<256, 256>>>(x);
    k_tail<<<128, 256>>>(w, it, out);
}

// round 16
// speedup vs baseline: 1.1967x; 1.1967x over previous
#include <cuda_runtime.h>
#include <cstdint>

#define MN       1024
#define BATCH    2048
#define DIM      128
#define NITER_F  100.0f
#define ALPHA_F  0.3f
#define SIGMA_F  16.0f

// ---------------- scratch ----------------
__device__ unsigned long long g_part[8][BATCH];  // per-m-block argmin partials
__device__ float g_S[MN * DIM];
__device__ float g_cnt[MN];

__device__ __forceinline__ unsigned int f2ord(float f) {
    unsigned int u = __float_as_uint(f);
    return (u & 0x80000000u) ? ~u : (u | 0x80000000u);
}

__device__ __forceinline__ unsigned long long dupf(float f) {
    unsigned long long r;
    unsigned int u = __float_as_uint(f);
    asm("mov.b64 %0, {%1, %1};" : "=l"(r) : "r"(u));
    return r;
}

__device__ __forceinline__ void ffma2(unsigned long long& acc,
                                      unsigned long long a,
                                      unsigned long long b) {
    asm("fma.rn.f32x2 %0, %1, %2, %0;" : "+l"(acc) : "l"(a), "l"(b));
}

// ---------------- K1: BMU GEMM + argmin (R2 geometry, prep folded in) -------
// block tile: 128 m x 64 b, 256 threads, each thread 8m x 4b via FFMA2.
// d2'(m,b) = w2[m] - 2 * dot(w[m], x[b])   (x2 dropped: constant per b)
#define WSP 132   // Ws row stride in floats (16B-aligned rows)
#define XSP 68    // Xs row stride in floats

__global__ __launch_bounds__(256, 2)
void k_bmu(const float* __restrict__ x, const float* __restrict__ w) {
    __shared__ float Ws[32 * WSP];                 // [kk][m]
    __shared__ float Xs[32 * XSP];                 // [kk][b]
    __shared__ unsigned long long Red[16][64];     // argmin reduction buffer
    __shared__ float w2s[128];

    const int m0 = blockIdx.x * 128;
    const int b0 = blockIdx.y * 64;
    const int tid = threadIdx.x;
    const int ty = tid >> 4;          // 0..15 -> m group
    const int tx = tid & 15;          // 0..15 -> b group
    const int tm = ty * 8;
    const int tb = tx * 4;

    // fold scratch zeroing into this kernel (256 blocks x 512 floats = all g_S)
    {
        int z = blockIdx.y * 8 + blockIdx.x;            // 0..255
        if (tid < 128)
            *(float4*)&g_S[z * 512 + tid * 4] = make_float4(0.f, 0.f, 0.f, 0.f);
        if (tid == 255)
            *(float4*)&g_cnt[z * 4] = make_float4(0.f, 0.f, 0.f, 0.f);
    }

    // w2 for this block's 128 cells (fp32, L2-resident)
    if (tid < 128) {
        float s = 0.0f;
        #pragma unroll
        for (int g = 0; g < 32; g++) {
            float4 v = *(const float4*)&w[(m0 + tid) * DIM + g * 4];
            s += v.x * v.x + v.y * v.y + v.z * v.z + v.w * v.w;
        }
        w2s[tid] = s;
    }

    // acc[p][j]: f32x2 pair for m = tm+2p, tm+2p+1 ; column b0+tb+j
    unsigned long long acc[4][4];
    #pragma unroll
    for (int p = 0; p < 4; p++)
        #pragma unroll
        for (int j = 0; j < 4; j++) acc[p][j] = 0ULL;

    for (int kc = 0; kc < DIM; kc += 32) {
        __syncthreads();
        // stage W tile transposed: 128 rows(m) x 32 cols(k)
        #pragma unroll
        for (int i = 0; i < 4; i++) {
            int idx = tid + i * 256;          // 0..1023 float4s
            int row = idx >> 3;               // m row 0..127
            int c4  = idx & 7;                // float4 col
            float4 v = *(const float4*)&w[(m0 + row) * DIM + kc + c4 * 4];
            Ws[(c4 * 4 + 0) * WSP + row] = v.x;
            Ws[(c4 * 4 + 1) * WSP + row] = v.y;
            Ws[(c4 * 4 + 2) * WSP + row] = v.z;
            Ws[(c4 * 4 + 3) * WSP + row] = v.w;
        }
        // stage X tile transposed: 64 rows(b) x 32 cols(k)
        #pragma unroll
        for (int i = 0; i < 2; i++) {
            int idx = tid + i * 256;          // 0..511 float4s
            int row = idx >> 3;               // b row 0..63
            int c4  = idx & 7;
            float4 v = *(const float4*)&x[(b0 + row) * DIM + kc + c4 * 4];
            Xs[(c4 * 4 + 0) * XSP + row] = v.x;
            Xs[(c4 * 4 + 1) * XSP + row] = v.y;
            Xs[(c4 * 4 + 2) * XSP + row] = v.z;
            Xs[(c4 * 4 + 3) * XSP + row] = v.w;
        }
        __syncthreads();

        #pragma unroll 8
        for (int kk = 0; kk < 32; kk++) {
            // w pairs come packed straight out of the 128-bit shared loads
            ulonglong2 wp01 = *(const ulonglong2*)&Ws[kk * WSP + tm];
            ulonglong2 wp23 = *(const ulonglong2*)&Ws[kk * WSP + tm + 4];
            float4 xv = *(const float4*)&Xs[kk * XSP + tb];
            unsigned long long xd0 = dupf(xv.x);
            unsigned long long xd1 = dupf(xv.y);
            unsigned long long xd2 = dupf(xv.z);
            unsigned long long xd3 = dupf(xv.w);
            ffma2(acc[0][0], wp01.x, xd0); ffma2(acc[0][1], wp01.x, xd1);
            ffma2(acc[0][2], wp01.x, xd2); ffma2(acc[0][3], wp01.x, xd3);
            ffma2(acc[1][0], wp01.y, xd0); ffma2(acc[1][1], wp01.y, xd1);
            ffma2(acc[1][2], wp01.y, xd2); ffma2(acc[1][3], wp01.y, xd3);
            ffma2(acc[2][0], wp23.x, xd0); ffma2(acc[2][1], wp23.x, xd1);
            ffma2(acc[2][2], wp23.x, xd2); ffma2(acc[2][3], wp23.x, xd3);
            ffma2(acc[3][0], wp23.y, xd0); ffma2(acc[3][1], wp23.y, xd1);
            ffma2(acc[3][2], wp23.y, xd2); ffma2(acc[3][3], wp23.y, xd3);
        }
    }

    // epilogue: d2' = w2[m] - 2*dot; pack keys, per-thread min over 8 m
    float w2r[8];
    #pragma unroll
    for (int i = 0; i < 8; i++) w2r[i] = w2s[tm + i];

    #pragma unroll
    for (int j = 0; j < 4; j++) {
        unsigned long long best = 0xFFFFFFFFFFFFFFFFULL;
        #pragma unroll
        for (int p = 0; p < 4; p++) {
            float lo = __uint_as_float((unsigned int)(acc[p][j]));
            float hi = __uint_as_float((unsigned int)(acc[p][j] >> 32));
            float d2a = w2r[2 * p]     - 2.0f * lo;
            float d2b = w2r[2 * p + 1] - 2.0f * hi;
            unsigned long long ka = ((unsigned long long)f2ord(d2a) << 32)
                                  | (unsigned long long)(m0 + tm + 2 * p);
            unsigned long long kb = ((unsigned long long)f2ord(d2b) << 32)
                                  | (unsigned long long)(m0 + tm + 2 * p + 1);
            best = min(best, min(ka, kb));
        }
        Red[ty][tb + j] = best;
    }
    __syncthreads();

    if (tid < 64) {
        unsigned long long best = Red[0][tid];
        #pragma unroll
        for (int t = 1; t < 16; t++) best = min(best, Red[t][tid]);
        g_part[blockIdx.x][b0 + tid] = best;   // plain store, no atomics
    }
}

// ---------------- K2: reduce partials + scatter x rows into BMU bins --------
__global__ void k_scatter(const float* __restrict__ x) {
    int warp = (blockIdx.x * blockDim.x + threadIdx.x) >> 5;  // 0..2047
    int lane = threadIdx.x & 31;
    if (warp >= BATCH) return;

    unsigned long long v = (lane < 8) ? g_part[lane][warp]
                                      : 0xFFFFFFFFFFFFFFFFULL;
    #pragma unroll
    for (int o = 4; o >= 1; o >>= 1)
        v = min(v, __shfl_xor_sync(0xffffffffu, v, o));
    v = __shfl_sync(0xffffffffu, v, 0);
    int m = (int)(v & 0xFFFFFFFFULL);

    float4 vv = *(const float4*)&x[warp * DIM + lane * 4];
    float* dst = &g_S[m * DIM + lane * 4];
    asm volatile("red.global.add.v4.f32 [%0], {%1, %2, %3, %4};"
                 :: "l"(dst), "f"(vv.x), "f"(vv.y), "f"(vv.z), "f"(vv.w)
                 : "memory");
    if (lane == 0) atomicAdd(&g_cnt[m], 1.0f);
}

// ---------------- K3: fused separable gaussian contraction + update ---------
// 128 blocks = (cx, d-quarter), 256 threads.
__global__ __launch_bounds__(256)
void k_tail(const float* __restrict__ w,
            const int* __restrict__ it,
            float* __restrict__ out) {
    __shared__ float4 Ts[32][9];     // [by][dq], padded
    __shared__ float tc_s[32];
    __shared__ float e_s[32];

    const int cx = blockIdx.x & 31;
    const int d0 = (blockIdx.x >> 5) * 32;   // d-quarter base
    const int tid = threadIdx.x;

    float lr_decay = 1.0f - (float)it[0] / NITER_F;
    float alpha_op = ALPHA_F * lr_decay;
    float sig = SIGMA_F * lr_decay;
    float inv_s2 = 1.0f / (sig * sig);

    if (tid < 32) e_s[tid] = expf(-(float)(tid * tid) * inv_s2);
    __syncthreads();

    // stage A: Ts[by][d] = sum_bx e(|cx-bx|) * S[by*32+bx][d]
    {
        const int by = tid >> 3;           // 0..31
        const int dq = tid & 7;            // float4 index
        const int d  = d0 + dq * 4;
        float4 a = make_float4(0.f, 0.f, 0.f, 0.f);
        #pragma unroll
        for (int bb = 0; bb < 4; bb++) {
            float4 sv[8];
            #pragma unroll
            for (int j = 0; j < 8; j++)
                sv[j] = *(const float4*)&g_S[(by * 32 + bb * 8 + j) * DIM + d];
            #pragma unroll
            for (int j = 0; j < 8; j++) {
                float e = e_s[abs(cx - (bb * 8 + j))];
                a.x += e * sv[j].x; a.y += e * sv[j].y;
                a.z += e * sv[j].z; a.w += e * sv[j].w;
            }
        }
        Ts[by][dq] = a;
    }
    if (tid < 32) {
        float c = 0.0f;
        #pragma unroll
        for (int bx = 0; bx < 32; bx++)
            c += e_s[abs(cx - bx)] * g_cnt[tid * 32 + bx];
        tc_s[tid] = c;
    }
    __syncthreads();

    // stage B
    {
        const int cy = tid >> 3;
        const int dq = tid & 7;
        const int d  = d0 + dq * 4;
        float4 a = make_float4(0.f, 0.f, 0.f, 0.f);
        float s = 0.0f;
        #pragma unroll
        for (int by = 0; by < 32; by++) {
            float e = e_s[abs(cy - by)];
            float4 t = Ts[by][dq];
            a.x += e * t.x; a.y += e * t.y;
            a.z += e * t.z; a.w += e * t.w;
            s += e * tc_s[by];
        }
        const int c = (cy * 32 + cx) * DIM + d;
        float4 wv = *(const float4*)&w[c];
        float4 o;
        o.x = wv.x + alpha_op * (a.x - s * wv.x);
        o.y = wv.y + alpha_op * (a.y - s * wv.y);
        o.z = wv.z + alpha_op * (a.z - s * wv.z);
        o.w = wv.w + alpha_op * (a.w - s * wv.w);
        *(float4*)&out[c] = o;
    }
}

// ---------------- launch ----------------
extern "C" void kernel_launch(void* const* d_in, const int* in_sizes, int n_in,
                              void* d_out, int out_size) {
    const float* x   = (const float*)d_in[0];   // [2048,128]
    const float* w   = (const float*)d_in[1];   // [1024,128]
    const int*   it  = (const int*)d_in[3];
    float* out = (float*)d_out;

    k_bmu<<<dim3(8, 32), 256>>>(x, w);
    k_scatter<<<256, 256>>>(x);
    k_tail<<<128, 256>>>(w, it, out);
}